// round 11
// baseline (speedup 1.0000x reference)
#include <cuda_runtime.h>
#include <cuda_bf16.h>
#include <math.h>

// ---------------------------------------------------------------------------
// FARGAN: 100 frames x 4 subframes recurrent vocoder, B=64.
// Phase A: frame conv hoisted out of the sequential loop (3 fp32 GEMMs).
// Phase P: weight repack into coalesced [K/4][Nout][4] layout.
// Phase B: persistent recurrent kernel: 32 CTAs x 512 threads, TWO chains
//          per CTA (R5 stage structure; every weight load feeds both chains,
//          amortizing the fixed per-step overhead across two batches).
// ---------------------------------------------------------------------------

#define FRN 100

// Scratch (device globals: allocation-free rule)
__device__ float g_X [6400 * 256];
__device__ float g_H1[6400 * 256];
__device__ float g_H2[6400 * 256];
__device__ float g_C [6400 * 512];
__device__ int   g_P [6400];
__device__ float g_Wp[217344];   // packed recurrent weights

// Packed weight offsets (floats)
#define OFF_FW    0        // Wfw   64 x 388
#define OFF_FWG   24832    // Wfwg  64 x 64
#define OFF_IH1   28928    // Wih1 192 x 128
#define OFF_HH1   53504    // Whh1 192 x 64
#define OFF_IH2   65792
#define OFF_HH2   90368
#define OFF_IH3   102656
#define OFF_HH3   127232
#define OFF_G1    139520   // Wg 64 x 64
#define OFF_G2    143616
#define OFF_G3    147712
#define OFF_SD    151808   // Wsd 128 x 320
#define OFF_SG    192768   // Wsg 128 x 128
#define OFF_OUT   209152   // Wout 64 x 128

// ---------------------------------------------------------------------------
__global__ void pack_kernel(const float* __restrict__ feats,
                            const float* __restrict__ gf)
{
    int m = blockIdx.x;              // b*100 + t
    int b = m / FRN, t = m % FRN;
    int c = threadIdx.x;             // 0..255
    float v;
    if (c < 192) v = feats[b * 193 * FRN + c * FRN + t];
    else         v = gf[b * 64 + (c - 192)];
    g_X[m * 256 + c] = v;
    if (c == 0)
        g_P[m] = (int)rintf(feats[b * 193 * FRN + 192 * FRN + t]);
}

__global__ void pack_w_kernel(const float* __restrict__ src,
                              float* __restrict__ dst, int Nout, int K)
{
    int i = blockIdx.x * blockDim.x + threadIdx.x;
    if (i >= Nout * K) return;
    int r = i / K, k = i % K;
    int k4 = k >> 2, c = k & 3;
    dst[(k4 * Nout + r) * 4 + c] = src[i];
}

// ---------------------------------------------------------------------------
// Tiled NT GEMM with fused tanh
// ---------------------------------------------------------------------------
#define GBM 64
#define GBN 64
#define GBK 16
__global__ __launch_bounds__(256) void gemm_nt_tanh(
    const float* __restrict__ A, const float* __restrict__ W,
    float* __restrict__ C, int M, int N, int K)
{
    __shared__ float As[GBK][GBM];
    __shared__ float Ws[GBK][GBN];
    const int tid = threadIdx.x;
    const int tx = tid & 15, ty = tid >> 4;
    const int row0 = blockIdx.y * GBM;
    const int col0 = blockIdx.x * GBN;

    float acc[4][4] = {};
    for (int k0 = 0; k0 < K; k0 += GBK) {
        #pragma unroll
        for (int i = tid; i < GBM * GBK; i += 256) {
            int r = i / GBK, kk = i % GBK;
            As[kk][r] = A[(row0 + r) * K + k0 + kk];
            Ws[kk][r] = W[(col0 + r) * K + k0 + kk];
        }
        __syncthreads();
        #pragma unroll
        for (int kk = 0; kk < GBK; kk++) {
            float4 a4 = *reinterpret_cast<const float4*>(&As[kk][ty * 4]);
            float4 b4 = *reinterpret_cast<const float4*>(&Ws[kk][tx * 4]);
            float a[4] = {a4.x, a4.y, a4.z, a4.w};
            float bv[4] = {b4.x, b4.y, b4.z, b4.w};
            #pragma unroll
            for (int i = 0; i < 4; i++)
                #pragma unroll
                for (int j = 0; j < 4; j++)
                    acc[i][j] = fmaf(a[i], bv[j], acc[i][j]);
        }
        __syncthreads();
    }
    #pragma unroll
    for (int i = 0; i < 4; i++)
        #pragma unroll
        for (int j = 0; j < 4; j++)
            C[(size_t)(row0 + ty * 4 + i) * N + col0 + tx * 4 + j] = tanhf(acc[i][j]);
}

// ---------------------------------------------------------------------------
// Recurrent kernel helpers
// ---------------------------------------------------------------------------
__device__ __forceinline__ float sigm(float x) { return 1.0f / (1.0f + expf(-x)); }

// Dual-chain partial dot, compile-time count. One weight load, two x streams.
template <int CNT>
__device__ __forceinline__ void pdot2f(const float4* __restrict__ W, int NOUT,
                                       const float* __restrict__ x0,
                                       const float* __restrict__ x1,
                                       int r, int k0, float& o0, float& o1)
{
    const float4* x04 = reinterpret_cast<const float4*>(x0);
    const float4* x14 = reinterpret_cast<const float4*>(x1);
    float4 a0 = {0.f,0.f,0.f,0.f}, a1 = {0.f,0.f,0.f,0.f};
    #pragma unroll
    for (int i = 0; i < CNT; i++) {
        int k = k0 + i;
        float4 w  = W[k * NOUT + r];
        float4 xa = x04[k];
        float4 xb = x14[k];
        a0.x = fmaf(w.x, xa.x, a0.x); a0.y = fmaf(w.y, xa.y, a0.y);
        a0.z = fmaf(w.z, xa.z, a0.z); a0.w = fmaf(w.w, xa.w, a0.w);
        a1.x = fmaf(w.x, xb.x, a1.x); a1.y = fmaf(w.y, xb.y, a1.y);
        a1.z = fmaf(w.z, xb.z, a1.z); a1.w = fmaf(w.w, xb.w, a1.w);
    }
    o0 = (a0.x + a0.y) + (a0.z + a0.w);
    o1 = (a1.x + a1.y) + (a1.z + a1.w);
}

// Dual-chain partial dot, runtime count (Wfw slices: 12 or 13).
__device__ __forceinline__ void pdot2r(const float4* __restrict__ W, int NOUT,
                                       const float* __restrict__ x0,
                                       const float* __restrict__ x1,
                                       int r, int k0, int cnt,
                                       float& o0, float& o1)
{
    const float4* x04 = reinterpret_cast<const float4*>(x0);
    const float4* x14 = reinterpret_cast<const float4*>(x1);
    float4 a0 = {0.f,0.f,0.f,0.f}, a1 = {0.f,0.f,0.f,0.f};
    #pragma unroll 4
    for (int k = k0; k < k0 + cnt; k++) {
        float4 w  = W[k * NOUT + r];
        float4 xa = x04[k];
        float4 xb = x14[k];
        a0.x = fmaf(w.x, xa.x, a0.x); a0.y = fmaf(w.y, xa.y, a0.y);
        a0.z = fmaf(w.z, xa.z, a0.z); a0.w = fmaf(w.w, xa.w, a0.w);
        a1.x = fmaf(w.x, xb.x, a1.x); a1.y = fmaf(w.y, xb.y, a1.y);
        a1.z = fmaf(w.z, xb.z, a1.z); a1.w = fmaf(w.w, xb.w, a1.w);
    }
    o0 = (a0.x + a0.y) + (a0.z + a0.w);
    o1 = (a1.x + a1.y) + (a1.z + a1.w);
}

// Dynamic SMEM layout (~202 KB)
struct __align__(16) SM {
    // SMEM-cached small weights (packed layout preserved), shared by chains
    float wfwg[4096];
    float wg[3][4096];
    float wout[8192];
    float wsg[16384];
    // per-chain state
    float prev[2][512];
    float v[2][388];
    float sfw[2][128];
    float xg[2][128];
    float st[2][3][64];
    float sk[2][320];
    float sd[2][128];
    float so[2][128];
    float tmp[2][64];
    // partial buffers, per chain
    float pb_fw[2][512];      // Wfw slices; reused for SG (4x128) and OUT (8x64)
    float pb_gh[2][3][192];   // Whh @ st      (mega)
    float pb_gip[2][3][192];  // Wih[:,64:128] @ prev_sub (mega)
    float pb_gic[2][2][192];  // Wih[:,0:64] @ cur (2 k-slices)
    float pb_sd[2][6][128];   // Wsd: [0]=prev [1]=fw [2]=o1 [3]=o2 [4,5]=o3
};

__global__ __launch_bounds__(512, 1) void recur_kernel(
    const float* __restrict__ prev_in,
    const float* __restrict__ Wp,
    float* __restrict__ outbuf)
{
    extern __shared__ unsigned char smem_raw[];
    SM& SL = *reinterpret_cast<SM*>(smem_raw);

    const int tid = threadIdx.x;
    const int b0 = blockIdx.x * 2;

    const float4* Wfw4 = (const float4*)(Wp + OFF_FW);
    const float4* Wih4[3] = {(const float4*)(Wp + OFF_IH1),
                             (const float4*)(Wp + OFF_IH2),
                             (const float4*)(Wp + OFF_IH3)};
    const float4* Whh4[3] = {(const float4*)(Wp + OFF_HH1),
                             (const float4*)(Wp + OFF_HH2),
                             (const float4*)(Wp + OFF_HH3)};
    const float4* Wsd4 = (const float4*)(Wp + OFF_SD);

    // One-time: copy small weight matrices into SMEM
    {
        const float4* s1 = (const float4*)(Wp + OFF_FWG);
        float4* d1 = (float4*)SL.wfwg;
        for (int i = tid; i < 1024; i += 512) d1[i] = s1[i];
        #pragma unroll
        for (int m = 0; m < 3; m++) {
            const float4* s2 = (const float4*)(Wp + (m == 0 ? OFF_G1 : m == 1 ? OFF_G2 : OFF_G3));
            float4* d2 = (float4*)SL.wg[m];
            for (int i = tid; i < 1024; i += 512) d2[i] = s2[i];
        }
        const float4* s3 = (const float4*)(Wp + OFF_OUT);
        float4* d3 = (float4*)SL.wout;
        for (int i = tid; i < 2048; i += 512) d3[i] = s3[i];
        const float4* s4 = (const float4*)(Wp + OFF_SG);
        float4* d4 = (float4*)SL.wsg;
        for (int i = tid; i < 4096; i += 512) d4[i] = s4[i];
    }

    // init: previous samples + zero states
    for (int i = tid; i < 1024; i += 512)
        SL.prev[i >> 9][i & 511] = prev_in[(b0 + (i >> 9)) * 512 + (i & 511)];
    if (tid < 384) SL.st[tid / 192][(tid % 192) >> 6][tid & 63] = 0.f;
    for (int i = tid; i < 256; i += 512) SL.sfw[i >> 7][i & 127] = 0.f;
    __syncthreads();

    const float4* WfwgS = (const float4*)SL.wfwg;
    const float4* WgS[3] = {(const float4*)SL.wg[0], (const float4*)SL.wg[1],
                            (const float4*)SL.wg[2]};
    const float4* WoutS = (const float4*)SL.wout;
    const float4* WsgS  = (const float4*)SL.wsg;

    for (int t = 0; t < FRN; t++) {
        const int p0 = g_P[(b0 + 0) * FRN + t];
        const int p1 = g_P[(b0 + 1) * FRN + t];
        for (int k = 0; k < 4; k++) {
            const int step = t * 4 + k;
            const int head = (step * 64) & 511;

            // --- Stage A: build v, xg[64:128], sk[256:320] for both chains
            for (int i = tid; i < 2 * 388; i += 512) {
                const int b = (i >= 388);
                const int j = i - b * 388;
                const int p = b ? p1 : p0;
                float val;
                if (j < 128) {
                    val = g_C[(size_t)((b0 + b) * FRN + t) * 512 + 4 * j + k];
                } else if (j < 192) {
                    int jj = j - 128;
                    val = SL.prev[b][(head + 448 + jj) & 511];   // prev_sub
                    SL.xg[b][64 + jj] = val;
                    SL.sk[b][256 + jj] = val;
                } else if (j < 260) {
                    int jj = j - 192;
                    int li = 510 - p + jj;
                    if (li >= 512) li -= p;
                    val = SL.prev[b][(head + li) & 511];          // lookback
                } else {
                    val = SL.sfw[b][j - 260];
                }
                SL.v[b][j] = val;
            }
            __syncthreads();

            // --- MEGA: Wfw slices + gh + gip + sd_prev (dual-chain dots)
            {
                int s = tid >> 6, r = tid & 63;
                int cnt = 12 + (s == 0);
                int k0 = s * 12 + (s > 0);
                float o0, o1;
                pdot2r(Wfw4, 64, SL.v[0], SL.v[1], r, k0, cnt, o0, o1);
                SL.pb_fw[0][s * 64 + r] = o0; SL.pb_fw[1][s * 64 + r] = o1;
            }
            #pragma unroll
            for (int pass = 0; pass < 3; pass++) {
                int id = tid + pass * 512;
                if (id < 576) {
                    int gr = (id >= 384) ? 2 : (id >= 192) ? 1 : 0;
                    int r = id - gr * 192;
                    float o0, o1;
                    pdot2f<16>(Whh4[gr], 192, SL.st[0][gr], SL.st[1][gr], r, 0, o0, o1);
                    SL.pb_gh[0][gr][r] = o0; SL.pb_gh[1][gr][r] = o1;
                } else if (id < 1152) {
                    int id2 = id - 576;
                    int gr = (id2 >= 384) ? 2 : (id2 >= 192) ? 1 : 0;
                    int r = id2 - gr * 192;
                    float o0, o1;
                    pdot2f<16>(Wih4[gr], 192, SL.xg[0], SL.xg[1], r, 16, o0, o1);
                    SL.pb_gip[0][gr][r] = o0; SL.pb_gip[1][gr][r] = o1;
                } else if (id < 1280) {
                    int r = id - 1152;
                    float o0, o1;
                    pdot2f<16>(Wsd4, 128, SL.sk[0], SL.sk[1], r, 64, o0, o1);
                    SL.pb_sd[0][0][r] = o0; SL.pb_sd[1][0][r] = o1;
                }
            }
            __syncthreads();

            // --- fw reduce + tanh
            if (tid < 128) {
                int b = tid >> 6, r = tid & 63;
                float s = 0.f;
                #pragma unroll
                for (int i = 0; i < 8; i++) s += SL.pb_fw[b][i * 64 + r];
                SL.tmp[b][r] = tanhf(s);
            }
            __syncthreads();
            // --- fw = GLU(tmp, Wfw_g) [SMEM], dual-chain on 64 threads
            if (tid < 64) {
                float g0, g1;
                pdot2f<16>(WfwgS, 64, SL.tmp[0], SL.tmp[1], tid, 0, g0, g1);
                float f0 = SL.tmp[0][tid] * sigm(g0);
                float f1 = SL.tmp[1][tid] * sigm(g1);
                SL.sk[0][192 + tid] = f0; SL.xg[0][tid] = f0;
                SL.sk[1][192 + tid] = f1; SL.xg[1][tid] = f1;
            }
            __syncthreads();

            // --- 3 GRU + GLU blocks
            #pragma unroll
            for (int gr = 0; gr < 3; gr++) {
                if (tid < 384) {
                    int s = tid / 192, r = tid % 192;
                    float o0, o1;
                    pdot2f<8>(Wih4[gr], 192, SL.xg[0], SL.xg[1], r, s * 8, o0, o1);
                    SL.pb_gic[0][s][r] = o0; SL.pb_gic[1][s][r] = o1;
                } else {
                    int r = tid - 384;
                    int k0 = (gr == 0) ? 48 : (gr == 1) ? 0 : 16;
                    float o0, o1;
                    pdot2f<16>(Wsd4, 128, SL.sk[0], SL.sk[1], r, k0, o0, o1);
                    SL.pb_sd[0][1 + gr][r] = o0; SL.pb_sd[1][1 + gr][r] = o1;
                }
                __syncthreads();
                if (tid < 128) {
                    int b = tid >> 6, j = tid & 63;
                    float gir = SL.pb_gic[b][0][j]       + SL.pb_gic[b][1][j]       + SL.pb_gip[b][gr][j];
                    float giz = SL.pb_gic[b][0][64 + j]  + SL.pb_gic[b][1][64 + j]  + SL.pb_gip[b][gr][64 + j];
                    float gin = SL.pb_gic[b][0][128 + j] + SL.pb_gic[b][1][128 + j] + SL.pb_gip[b][gr][128 + j];
                    float r_ = sigm(gir + SL.pb_gh[b][gr][j]);
                    float z  = sigm(giz + SL.pb_gh[b][gr][64 + j]);
                    float n  = tanhf(gin + r_ * SL.pb_gh[b][gr][128 + j]);
                    SL.st[b][gr][j] = (1.f - z) * n + z * SL.st[b][gr][j];
                }
                __syncthreads();
                if (tid < 64) {
                    float g0, g1;
                    pdot2f<16>(WgS[gr], 64, SL.st[0][gr], SL.st[1][gr], tid, 0, g0, g1);
                    float o0 = SL.st[0][gr][tid] * sigm(g0);
                    float o1 = SL.st[1][gr][tid] * sigm(g1);
                    SL.sk[0][gr * 64 + tid] = o0;
                    SL.sk[1][gr * 64 + tid] = o1;
                    if (gr < 2) { SL.xg[0][tid] = o0; SL.xg[1][tid] = o1; }
                }
                __syncthreads();
            }

            // --- Wsd final slice (o3), dual-chain
            if (tid < 256) {
                int r = tid & 127, s = tid >> 7;
                float o0, o1;
                pdot2f<8>(Wsd4, 128, SL.sk[0], SL.sk[1], r, 32 + s * 8, o0, o1);
                SL.pb_sd[0][4 + s][r] = o0; SL.pb_sd[1][4 + s][r] = o1;
            }
            __syncthreads();
            if (tid < 256) {
                int b = tid >> 7, r = tid & 127;
                float sum = ((SL.pb_sd[b][2][r] + SL.pb_sd[b][3][r]) +
                             (SL.pb_sd[b][4][r] + SL.pb_sd[b][5][r])) +
                            (SL.pb_sd[b][1][r] + SL.pb_sd[b][0][r]);
                SL.sd[b][r] = tanhf(sum);
            }
            __syncthreads();

            // --- sg: gate partials (SMEM weights, 4 slices of 8), dual-chain
            {
                int r = tid & 127, s = tid >> 7;
                float o0, o1;
                pdot2f<8>(WsgS, 128, SL.sd[0], SL.sd[1], r, s * 8, o0, o1);
                SL.pb_fw[0][s * 128 + r] = o0; SL.pb_fw[1][s * 128 + r] = o1;
            }
            __syncthreads();
            if (tid < 256) {
                int b = tid >> 7, r = tid & 127;
                float g = (SL.pb_fw[b][r] + SL.pb_fw[b][128 + r]) +
                          (SL.pb_fw[b][256 + r] + SL.pb_fw[b][384 + r]);
                SL.so[b][r] = SL.sd[b][r] * sigm(g);
            }
            __syncthreads();

            // --- out: (SMEM weights, 8 slices of 4), dual-chain
            {
                int r = tid & 63, s = tid >> 6;
                float o0, o1;
                pdot2f<4>(WoutS, 64, SL.so[0], SL.so[1], r, s * 4, o0, o1);
                SL.pb_fw[0][s * 64 + r] = o0; SL.pb_fw[1][s * 64 + r] = o1;
            }
            __syncthreads();
            if (tid < 128) {
                int b = tid >> 6, r = tid & 63;
                float sum = 0.f;
                #pragma unroll
                for (int i = 0; i < 8; i++) sum += SL.pb_fw[b][i * 64 + r];
                float o = tanhf(sum);
                outbuf[(size_t)(b0 + b) * 25600 + (size_t)t * 256 + k * 64 + r] = o;
                SL.prev[b][(head + r) & 511] = o;
            } else if (tid < 384) {
                int i = tid - 128;          // 0..255: sfw <- feat2s
                int b = i >> 7, j = i & 127;
                SL.sfw[b][j] = SL.v[b][j];
            }
            __syncthreads();
        }
    }
}

// ---------------------------------------------------------------------------
extern "C" void kernel_launch(void* const* d_in, const int* in_sizes, int n_in,
                              void* d_out, int out_size)
{
    const float* features = (const float*)d_in[0];
    const float* gfeat    = (const float*)d_in[1];
    const float* prev     = (const float*)d_in[2];
    const float* Wc1      = (const float*)d_in[3];
    const float* Wc2      = (const float*)d_in[4];
    const float* Wc3      = (const float*)d_in[5];
    float* out = (float*)d_out;

    float *pX, *pH1, *pH2, *pC, *pWp;
    cudaGetSymbolAddress((void**)&pX,  g_X);
    cudaGetSymbolAddress((void**)&pH1, g_H1);
    cudaGetSymbolAddress((void**)&pH2, g_H2);
    cudaGetSymbolAddress((void**)&pC,  g_C);
    cudaGetSymbolAddress((void**)&pWp, g_Wp);

    // Phase P: repack recurrent weights into coalesced layout
    struct PW { int idx, off, nout, K; };
    const PW pw[14] = {
        { 6, OFF_FW,  64, 388}, { 7, OFF_FWG, 64,  64},
        { 8, OFF_IH1, 192, 128}, { 9, OFF_HH1, 192, 64},
        {10, OFF_IH2, 192, 128}, {11, OFF_HH2, 192, 64},
        {12, OFF_IH3, 192, 128}, {13, OFF_HH3, 192, 64},
        {14, OFF_G1,  64,  64}, {15, OFF_G2,  64,  64}, {16, OFF_G3, 64, 64},
        {17, OFF_SG, 128, 128}, {18, OFF_SD, 128, 320}, {19, OFF_OUT, 64, 128},
    };
    for (int i = 0; i < 14; i++) {
        int n = pw[i].nout * pw[i].K;
        pack_w_kernel<<<(n + 255) / 256, 256>>>((const float*)d_in[pw[i].idx],
                                                pWp + pw[i].off,
                                                pw[i].nout, pw[i].K);
    }

    // Phase A: frame-feature conv stack (not recurrent)
    pack_kernel<<<6400, 256>>>(features, gfeat);
    gemm_nt_tanh<<<dim3(4, 100), 256>>>(pX,  Wc1, pH1, 6400, 256, 256);
    gemm_nt_tanh<<<dim3(4, 100), 256>>>(pH1, Wc2, pH2, 6400, 256, 256);
    gemm_nt_tanh<<<dim3(8, 100), 256>>>(pH2, Wc3, pC,  6400, 512, 256);

    // Phase B: persistent recurrent kernel (2 chains per CTA)
    static const int SMEM_BYTES = (int)sizeof(SM);
    cudaFuncSetAttribute(recur_kernel,
                         cudaFuncAttributeMaxDynamicSharedMemorySize, SMEM_BYTES);
    recur_kernel<<<32, 512, SMEM_BYTES>>>(prev, pWp, out);
}

// round 16
// speedup vs baseline: 1.1882x; 1.1882x over previous
#include <cuda_runtime.h>
#include <cuda_bf16.h>
#include <math.h>

// ---------------------------------------------------------------------------
// FARGAN: 100 frames x 4 subframes recurrent vocoder, B=64.
// Phase A: frame conv hoisted out of the sequential loop (3 fp32 GEMMs).
// Phase P: ONE weight repack kernel ([K/4][Nout][4] layout) so recur is the
//          6th launch (ncu -s 5 captures it).
// Phase B: persistent recurrent kernel: 64 CTAs x 512 threads, one chain per
//          CTA (R5 structure) + warp-shuffle fused reductions: fw/sd/sg/out
//          reduce stages eliminated (19 -> 15 barriers per step).
// ---------------------------------------------------------------------------

#define FRN 100

// Scratch (device globals: allocation-free rule)
__device__ float g_X [6400 * 256];
__device__ float g_H1[6400 * 256];
__device__ float g_H2[6400 * 256];
__device__ float g_C [6400 * 512];
__device__ int   g_P [6400];
__device__ float g_Wp[217344];   // packed recurrent weights

// Packed weight offsets (floats)
#define OFF_FW    0        // Wfw   64 x 388
#define OFF_FWG   24832    // Wfwg  64 x 64
#define OFF_IH1   28928    // Wih1 192 x 128
#define OFF_HH1   53504    // Whh1 192 x 64
#define OFF_IH2   65792
#define OFF_HH2   90368
#define OFF_IH3   102656
#define OFF_HH3   127232
#define OFF_G1    139520   // Wg 64 x 64
#define OFF_G2    143616
#define OFF_G3    147712
#define OFF_SD    151808   // Wsd 128 x 320
#define OFF_SG    192768   // Wsg 128 x 128
#define OFF_OUT   209152   // Wout 64 x 128

// ---------------------------------------------------------------------------
__global__ void pack_kernel(const float* __restrict__ feats,
                            const float* __restrict__ gf)
{
    int m = blockIdx.x;              // b*100 + t
    int b = m / FRN, t = m % FRN;
    int c = threadIdx.x;             // 0..255
    float v;
    if (c < 192) v = feats[b * 193 * FRN + c * FRN + t];
    else         v = gf[b * 64 + (c - 192)];
    g_X[m * 256 + c] = v;
    if (c == 0)
        g_P[m] = (int)rintf(feats[b * 193 * FRN + 192 * FRN + t]);
}

// All 14 weight repacks in ONE launch (blockIdx.y = matrix id)
struct WPtrs { const float* p[14]; };
__global__ void pack_all_w(WPtrs wp, float* __restrict__ dst)
{
    const int offs[14]  = {OFF_FW, OFF_FWG, OFF_IH1, OFF_HH1, OFF_IH2, OFF_HH2,
                           OFF_IH3, OFF_HH3, OFF_G1, OFF_G2, OFF_G3,
                           OFF_SG, OFF_SD, OFF_OUT};
    const int nouts[14] = {64, 64, 192, 192, 192, 192, 192, 192,
                           64, 64, 64, 128, 128, 64};
    const int Ks[14]    = {388, 64, 128, 64, 128, 64, 128, 64,
                           64, 64, 64, 128, 320, 128};
    int m = blockIdx.y;
    int Nout = nouts[m], K = Ks[m];
    int i = blockIdx.x * blockDim.x + threadIdx.x;
    if (i >= Nout * K) return;
    int r = i / K, k = i % K;
    int k4 = k >> 2, c = k & 3;
    dst[offs[m] + (k4 * Nout + r) * 4 + c] = wp.p[m][i];
}

// ---------------------------------------------------------------------------
// Tiled NT GEMM with fused tanh
// ---------------------------------------------------------------------------
#define GBM 64
#define GBN 64
#define GBK 16
__global__ __launch_bounds__(256) void gemm_nt_tanh(
    const float* __restrict__ A, const float* __restrict__ W,
    float* __restrict__ C, int M, int N, int K)
{
    __shared__ float As[GBK][GBM];
    __shared__ float Ws[GBK][GBN];
    const int tid = threadIdx.x;
    const int tx = tid & 15, ty = tid >> 4;
    const int row0 = blockIdx.y * GBM;
    const int col0 = blockIdx.x * GBN;

    float acc[4][4] = {};
    for (int k0 = 0; k0 < K; k0 += GBK) {
        #pragma unroll
        for (int i = tid; i < GBM * GBK; i += 256) {
            int r = i / GBK, kk = i % GBK;
            As[kk][r] = A[(row0 + r) * K + k0 + kk];
            Ws[kk][r] = W[(col0 + r) * K + k0 + kk];
        }
        __syncthreads();
        #pragma unroll
        for (int kk = 0; kk < GBK; kk++) {
            float4 a4 = *reinterpret_cast<const float4*>(&As[kk][ty * 4]);
            float4 b4 = *reinterpret_cast<const float4*>(&Ws[kk][tx * 4]);
            float a[4] = {a4.x, a4.y, a4.z, a4.w};
            float bv[4] = {b4.x, b4.y, b4.z, b4.w};
            #pragma unroll
            for (int i = 0; i < 4; i++)
                #pragma unroll
                for (int j = 0; j < 4; j++)
                    acc[i][j] = fmaf(a[i], bv[j], acc[i][j]);
        }
        __syncthreads();
    }
    #pragma unroll
    for (int i = 0; i < 4; i++)
        #pragma unroll
        for (int j = 0; j < 4; j++)
            C[(size_t)(row0 + ty * 4 + i) * N + col0 + tx * 4 + j] = tanhf(acc[i][j]);
}

// ---------------------------------------------------------------------------
// Recurrent kernel helpers
// ---------------------------------------------------------------------------
__device__ __forceinline__ float sigm(float x) { return 1.0f / (1.0f + expf(-x)); }

template <int CNT>
__device__ __forceinline__ float pdotf(const float4* __restrict__ W, int NOUT,
                                       const float* __restrict__ x, int r, int k0)
{
    const float4* x4 = reinterpret_cast<const float4*>(x);
    float4 a = {0.f,0.f,0.f,0.f};
    #pragma unroll
    for (int i = 0; i < CNT; i++) {
        int k = k0 + i;
        float4 w  = W[k * NOUT + r];
        float4 xv = x4[k];
        a.x = fmaf(w.x, xv.x, a.x); a.y = fmaf(w.y, xv.y, a.y);
        a.z = fmaf(w.z, xv.z, a.z); a.w = fmaf(w.w, xv.w, a.w);
    }
    return (a.x + a.y) + (a.z + a.w);
}

__device__ __forceinline__ float pdotr(const float4* __restrict__ W, int NOUT,
                                       const float* __restrict__ x, int r,
                                       int k0, int cnt)
{
    const float4* x4 = reinterpret_cast<const float4*>(x);
    float4 a = {0.f,0.f,0.f,0.f};
    #pragma unroll 4
    for (int k = k0; k < k0 + cnt; k++) {
        float4 w  = W[k * NOUT + r];
        float4 xv = x4[k];
        a.x = fmaf(w.x, xv.x, a.x); a.y = fmaf(w.y, xv.y, a.y);
        a.z = fmaf(w.z, xv.z, a.z); a.w = fmaf(w.w, xv.w, a.w);
    }
    return (a.x + a.y) + (a.z + a.w);
}

// Dynamic SMEM layout (~170 KB)
struct __align__(16) SM {
    // SMEM-cached small weights (packed layout preserved)
    float wfwg[4096];
    float wg[3][4096];
    float wout[8192];
    float wsg[16384];
    // per-chain state
    float prev[512];
    float v[388];
    float sfw[128];
    float xg[128];
    float st[3][64];
    float sk[320];
    float sd[128];
    float so[128];
    float tmp[64];
    // partial buffers
    float pb_gh[3][192];    // Whh @ st          (mega)
    float pb_gip[3][192];   // Wih[:,64:128] @ prev_sub (mega)
    float pb_gic[192];      // Wih[:,0:64] @ cur (shuffle-summed in GI stage)
    float pb_sd[4][128];    // Wsd: [0]=prev [1]=fw [2]=o1 [3]=o2
};

__global__ __launch_bounds__(512, 1) void recur_kernel(
    const float* __restrict__ prev_in,
    const float* __restrict__ Wp,
    float* __restrict__ outbuf)
{
    extern __shared__ unsigned char smem_raw[];
    SM& SL = *reinterpret_cast<SM*>(smem_raw);

    const int tid = threadIdx.x;
    const int b = blockIdx.x;
    const int wrp = tid >> 5;
    const int lan = tid & 31;

    const float4* Wfw4 = (const float4*)(Wp + OFF_FW);
    const float4* Wih4[3] = {(const float4*)(Wp + OFF_IH1),
                             (const float4*)(Wp + OFF_IH2),
                             (const float4*)(Wp + OFF_IH3)};
    const float4* Whh4[3] = {(const float4*)(Wp + OFF_HH1),
                             (const float4*)(Wp + OFF_HH2),
                             (const float4*)(Wp + OFF_HH3)};
    const float4* Wsd4 = (const float4*)(Wp + OFF_SD);

    // One-time: copy small weight matrices into SMEM
    {
        const float4* s1 = (const float4*)(Wp + OFF_FWG);
        float4* d1 = (float4*)SL.wfwg;
        for (int i = tid; i < 1024; i += 512) d1[i] = s1[i];
        #pragma unroll
        for (int m = 0; m < 3; m++) {
            const float4* s2 = (const float4*)(Wp + (m == 0 ? OFF_G1 : m == 1 ? OFF_G2 : OFF_G3));
            float4* d2 = (float4*)SL.wg[m];
            for (int i = tid; i < 1024; i += 512) d2[i] = s2[i];
        }
        const float4* s3 = (const float4*)(Wp + OFF_OUT);
        float4* d3 = (float4*)SL.wout;
        for (int i = tid; i < 2048; i += 512) d3[i] = s3[i];
        const float4* s4 = (const float4*)(Wp + OFF_SG);
        float4* d4 = (float4*)SL.wsg;
        for (int i = tid; i < 4096; i += 512) d4[i] = s4[i];
    }

    // init: previous samples + zero states
    SL.prev[tid] = prev_in[b * 512 + tid];
    if (tid < 192) SL.st[tid >> 6][tid & 63] = 0.f;
    if (tid >= 192 && tid < 320) SL.sfw[tid - 192] = 0.f;
    __syncthreads();

    const float4* WfwgS = (const float4*)SL.wfwg;
    const float4* WgS[3] = {(const float4*)SL.wg[0], (const float4*)SL.wg[1],
                            (const float4*)SL.wg[2]};
    const float4* WoutS = (const float4*)SL.wout;
    const float4* WsgS  = (const float4*)SL.wsg;

    for (int t = 0; t < FRN; t++) {
        const int p = g_P[b * FRN + t];
        for (int k = 0; k < 4; k++) {
            const int head = ((t * 4 + k) * 64) & 511;

            // --- Stage A: build v, xg[64:128], sk[256:320]
            if (tid < 388) {
                const int j = tid;
                float val;
                if (j < 128) {
                    val = g_C[(size_t)(b * FRN + t) * 512 + 4 * j + k];
                } else if (j < 192) {
                    int jj = j - 128;
                    val = SL.prev[(head + 448 + jj) & 511];   // prev_sub
                    SL.xg[64 + jj] = val;
                    SL.sk[256 + jj] = val;
                } else if (j < 260) {
                    int jj = j - 192;
                    int li = 510 - p + jj;
                    if (li >= 512) li -= p;
                    val = SL.prev[(head + li) & 511];          // lookback
                } else {
                    val = SL.sfw[j - 260];
                }
                SL.v[j] = val;
            }
            __syncthreads();

            // --- MEGA: Wfw (shuffle-reduced) + gh + gip + sd_prev
            {
                // fw: row r = 4*wrp + (lan&3); slice s = lan>>2 (0..7)
                int r = 4 * wrp + (lan & 3);
                int s = lan >> 2;
                int cnt = 12 + (s == 0);
                int k0 = s * 12 + (s > 0);
                float part = pdotr(Wfw4, 64, SL.v, r, k0, cnt);
                part += __shfl_xor_sync(0xffffffffu, part, 4);
                part += __shfl_xor_sync(0xffffffffu, part, 8);
                part += __shfl_xor_sync(0xffffffffu, part, 16);
                if (lan < 4) SL.tmp[r] = tanhf(part);
            }
            #pragma unroll
            for (int pass = 0; pass < 3; pass++) {
                int id = tid + pass * 512;
                if (id < 576) {
                    int gr = (id >= 384) ? 2 : (id >= 192) ? 1 : 0;
                    int r = id - gr * 192;
                    SL.pb_gh[gr][r] = pdotf<16>(Whh4[gr], 192, SL.st[gr], r, 0);
                } else if (id < 1152) {
                    int id2 = id - 576;
                    int gr = (id2 >= 384) ? 2 : (id2 >= 192) ? 1 : 0;
                    int r = id2 - gr * 192;
                    SL.pb_gip[gr][r] = pdotf<16>(Wih4[gr], 192, SL.xg, r, 16);
                } else if (id < 1280) {
                    int r = id - 1152;
                    SL.pb_sd[0][r] = pdotf<16>(Wsd4, 128, SL.sk, r, 64);
                }
            }
            __syncthreads();

            // --- fw = GLU(tmp, Wfw_g) [SMEM]
            if (tid < 64) {
                float g = pdotf<16>(WfwgS, 64, SL.tmp, tid, 0);
                float f = SL.tmp[tid] * sigm(g);
                SL.sk[192 + tid] = f;
                SL.xg[tid] = f;
            }
            __syncthreads();

            // --- 3 GRU + GLU blocks
            #pragma unroll
            for (int gr = 0; gr < 3; gr++) {
                // GI (shuffle over 2 k-slices) + concurrent Wsd slice
                if (tid < 384) {
                    int r = 16 * wrp + (lan & 15);
                    int s = lan >> 4;
                    float part = pdotf<8>(Wih4[gr], 192, SL.xg, r, s * 8);
                    part += __shfl_xor_sync(0xffffffffu, part, 16);
                    if (lan < 16) SL.pb_gic[r] = part;
                } else {
                    int r = tid - 384;
                    int k0 = (gr == 0) ? 48 : (gr == 1) ? 0 : 16;
                    SL.pb_sd[1 + gr][r] = pdotf<16>(Wsd4, 128, SL.sk, r, k0);
                }
                __syncthreads();
                // ELEM
                if (tid < 64) {
                    int j = tid;
                    float r_ = sigm(SL.pb_gic[j]       + SL.pb_gip[gr][j]       + SL.pb_gh[gr][j]);
                    float z  = sigm(SL.pb_gic[64 + j]  + SL.pb_gip[gr][64 + j]  + SL.pb_gh[gr][64 + j]);
                    float n  = tanhf(SL.pb_gic[128 + j] + SL.pb_gip[gr][128 + j] + r_ * SL.pb_gh[gr][128 + j]);
                    SL.st[gr][j] = (1.f - z) * n + z * SL.st[gr][j];
                }
                __syncthreads();
                // GLU [SMEM]
                if (tid < 64) {
                    float g = pdotf<16>(WgS[gr], 64, SL.st[gr], tid, 0);
                    float o = SL.st[gr][tid] * sigm(g);
                    SL.sk[gr * 64 + tid] = o;
                    if (gr < 2) SL.xg[tid] = o;
                }
                __syncthreads();
            }

            // --- SDFINAL: o3 slices (shuffle) + full reduce + tanh
            if (tid < 256) {
                int r = 16 * wrp + (lan & 15);
                int s = lan >> 4;
                float part = pdotf<8>(Wsd4, 128, SL.sk, r, 32 + s * 8);
                part += __shfl_xor_sync(0xffffffffu, part, 16);
                if (lan < 16) {
                    float sum = (SL.pb_sd[2][r] + SL.pb_sd[3][r]) + part +
                                (SL.pb_sd[1][r] + SL.pb_sd[0][r]);
                    SL.sd[r] = tanhf(sum);
                }
            }
            __syncthreads();

            // --- SG: gate (shuffle over 4 slices) + GLU mul [SMEM]
            {
                int r = 8 * wrp + (lan & 7);
                int s = lan >> 3;
                float part = pdotf<8>(WsgS, 128, SL.sd, r, s * 8);
                part += __shfl_xor_sync(0xffffffffu, part, 8);
                part += __shfl_xor_sync(0xffffffffu, part, 16);
                if (lan < 8) SL.so[r] = SL.sd[r] * sigm(part);
            }
            __syncthreads();

            // --- OUT: (shuffle over 8 slices) + tanh + ring write + sfw copy
            {
                int r = 4 * wrp + (lan & 3);
                int s = lan >> 2;
                float part = pdotf<4>(WoutS, 64, SL.so, r, s * 4);
                part += __shfl_xor_sync(0xffffffffu, part, 4);
                part += __shfl_xor_sync(0xffffffffu, part, 8);
                part += __shfl_xor_sync(0xffffffffu, part, 16);
                if (lan < 4) {
                    float o = tanhf(part);
                    outbuf[(size_t)b * 25600 + (size_t)t * 256 + k * 64 + r] = o;
                    SL.prev[(head + r) & 511] = o;
                } else if (wrp < 8 && lan >= 4 && lan < 20) {
                    int j = wrp * 16 + (lan - 4);
                    SL.sfw[j] = SL.v[j];      // new sfw = current feat2s
                }
            }
            __syncthreads();
        }
    }
}

// ---------------------------------------------------------------------------
extern "C" void kernel_launch(void* const* d_in, const int* in_sizes, int n_in,
                              void* d_out, int out_size)
{
    const float* features = (const float*)d_in[0];
    const float* gfeat    = (const float*)d_in[1];
    const float* prev     = (const float*)d_in[2];
    const float* Wc1      = (const float*)d_in[3];
    const float* Wc2      = (const float*)d_in[4];
    const float* Wc3      = (const float*)d_in[5];
    float* out = (float*)d_out;

    float *pX, *pH1, *pH2, *pC, *pWp;
    cudaGetSymbolAddress((void**)&pX,  g_X);
    cudaGetSymbolAddress((void**)&pH1, g_H1);
    cudaGetSymbolAddress((void**)&pH2, g_H2);
    cudaGetSymbolAddress((void**)&pC,  g_C);
    cudaGetSymbolAddress((void**)&pWp, g_Wp);

    // Phase P: repack all recurrent weights in ONE launch
    // (order matches pack_all_w's offs[]: FW,FWG,IH1,HH1,IH2,HH2,IH3,HH3,
    //  G1,G2,G3,SG,SD,OUT)
    WPtrs wp;
    const int srcidx[14] = {6, 7, 8, 9, 10, 11, 12, 13, 14, 15, 16, 17, 18, 19};
    for (int i = 0; i < 14; i++) wp.p[i] = (const float*)d_in[srcidx[i]];
    pack_all_w<<<dim3(160, 14), 256>>>(wp, pWp);

    // Phase A: frame-feature conv stack (not recurrent)
    pack_kernel<<<6400, 256>>>(features, gfeat);
    gemm_nt_tanh<<<dim3(4, 100), 256>>>(pX,  Wc1, pH1, 6400, 256, 256);
    gemm_nt_tanh<<<dim3(4, 100), 256>>>(pH1, Wc2, pH2, 6400, 256, 256);
    gemm_nt_tanh<<<dim3(8, 100), 256>>>(pH2, Wc3, pC,  6400, 512, 256);

    // Phase B: persistent recurrent kernel (1 chain per CTA) — 6th launch
    static const int SMEM_BYTES = (int)sizeof(SM);
    cudaFuncSetAttribute(recur_kernel,
                         cudaFuncAttributeMaxDynamicSharedMemorySize, SMEM_BYTES);
    recur_kernel<<<64, 512, SMEM_BYTES>>>(prev, pWp, out);
}